// round 1
// baseline (speedup 1.0000x reference)
#include <cuda_runtime.h>
#include <cstdint>

// Problem constants (B=4, S=2048, D=1024, E=8, F=2048, top_k=2)
#define T_TOK 8192
#define D_DIM 1024
#define E_NUM 8
#define F_DIM 2048
#define RMAX  (2 * T_TOK)   // total expert-rows (each token in exactly 2 lists)

// ---------------- scratch (device globals; no allocation allowed) -----------
__device__ float g_H[(size_t)RMAX * F_DIM];   // 134 MB intermediate activations
__device__ int   g_rows_token[RMAX];
__device__ float g_rows_w[RMAX];
__device__ int   g_top_i[2 * T_TOK];
__device__ float g_top_w[2 * T_TOK];
__device__ int   g_counts[E_NUM];
__device__ int   g_offsets[E_NUM];
__device__ int   g_cursor[E_NUM];

// Packed f32x2 FMA (sm_100+; ptxas never auto-fuses — see SASS_QUICKREF)
__device__ __forceinline__ float2 ffma2(float2 a, float2 b, float2 c) {
    float2 d;
    asm("fma.rn.f32x2 %0, %1, %2, %3;"
        : "=l"(*reinterpret_cast<unsigned long long*>(&d))
        : "l"(*reinterpret_cast<unsigned long long*>(&a)),
          "l"(*reinterpret_cast<unsigned long long*>(&b)),
          "l"(*reinterpret_cast<unsigned long long*>(&c)));
    return d;
}

// ---------------- init: zero the tiny control arrays ------------------------
__global__ void init_kernel() {
    int i = threadIdx.x;
    if (i < E_NUM) { g_counts[i] = 0; g_cursor[i] = 0; }
}

// ---------------- router: one warp per token --------------------------------
__global__ void router_kernel(const float* __restrict__ x,
                              const int* __restrict__ mask,
                              const float* __restrict__ rw) {
    __shared__ float rws[E_NUM * D_DIM];   // transposed [e][d] — conflict-free reads
    for (int i = threadIdx.x; i < E_NUM * D_DIM; i += blockDim.x) {
        int d = i >> 3, e = i & 7;
        rws[e * D_DIM + d] = rw[i];        // rw is [D, E]
    }
    __syncthreads();

    int wid  = blockIdx.x * (blockDim.x >> 5) + (threadIdx.x >> 5);
    int lane = threadIdx.x & 31;
    if (wid >= T_TOK) return;

    const float* xp = x + (size_t)wid * D_DIM;
    float xr[32];
#pragma unroll
    for (int j = 0; j < 32; j++) xr[j] = xp[lane + 32 * j];

    float lg[E_NUM];
#pragma unroll
    for (int e = 0; e < E_NUM; e++) {
        float acc = 0.f;
#pragma unroll
        for (int j = 0; j < 32; j++)
            acc = fmaf(xr[j], rws[e * D_DIM + lane + 32 * j], acc);
#pragma unroll
        for (int o = 16; o; o >>= 1) acc += __shfl_xor_sync(0xffffffffu, acc, o);
        lg[e] = acc;
    }

    if (lane == 0) {
        // top-2 with earliest-index tie-break (matches jax top_k)
        int i0 = 0; float v0 = lg[0];
#pragma unroll
        for (int e = 1; e < E_NUM; e++) if (lg[e] > v0) { v0 = lg[e]; i0 = e; }
        int i1 = -1; float v1 = -3.0e38f;
#pragma unroll
        for (int e = 0; e < E_NUM; e++)
            if (e != i0 && lg[e] > v1) { v1 = lg[e]; i1 = e; }
        // renormalized top-2 softmax weights
        float r  = expf(v1 - v0);
        float s  = 1.f + r;
        float w0 = 1.f / s;
        float w1 = r / s;
        g_top_i[2 * wid] = i0;  g_top_i[2 * wid + 1] = i1;
        g_top_w[2 * wid] = w0;  g_top_w[2 * wid + 1] = w1;
        if (mask[wid] != 0) {
            atomicAdd(&g_counts[i0], 1);
            atomicAdd(&g_counts[i1], 1);
        }
    }
}

// ---------------- exclusive prefix over 8 counts ----------------------------
__global__ void offsets_kernel() {
    if (threadIdx.x == 0) {
        int s = 0;
        for (int e = 0; e < E_NUM; e++) { g_offsets[e] = s; s += g_counts[e]; }
    }
}

// ---------------- scatter tokens into per-expert lists ----------------------
__global__ void scatter_kernel(const int* __restrict__ mask) {
    int t = blockIdx.x * blockDim.x + threadIdx.x;
    if (t >= T_TOK) return;
    if (mask[t] == 0) return;
#pragma unroll
    for (int k = 0; k < 2; k++) {
        int e   = g_top_i[2 * t + k];
        int pos = atomicAdd(&g_cursor[e], 1);
        int idx = g_offsets[e] + pos;
        g_rows_token[idx] = t;
        g_rows_w[idx]     = g_top_w[2 * t + k];
    }
}

// ---------------- grouped GEMM tile params ----------------------------------
#define BM 128
#define BN 128
#define BK 16
#define AS_LD 260   // padded duplicated-A row (floats); keeps 16B alignment

// GEMM1: H[r, :] = relu(x[tok(r), :] @ w1[e] + b1[e]),  K = D_DIM
__global__ __launch_bounds__(256, 2)
void gemm1_kernel(const float* __restrict__ x,
                  const float* __restrict__ w1,
                  const float* __restrict__ b1) {
    int e    = blockIdx.z;
    int n_e  = g_counts[e];
    int row0 = blockIdx.y * BM;
    if (row0 >= n_e) return;
    int base = g_offsets[e];
    int n0   = blockIdx.x * BN;

    __shared__ float As2[BK][AS_LD];   // duplicated: As2[k][2m] == As2[k][2m+1]
    __shared__ float Bs[BK][BN];
    __shared__ int   tok_s[BM];

    int tid = threadIdx.x;
    if (tid < BM) {
        int r = row0 + tid;
        tok_s[tid] = (r < n_e) ? g_rows_token[base + r] : -1;
    }
    __syncthreads();

    const float* Bsrc = w1 + (size_t)e * D_DIM * F_DIM + n0;
    int ty = tid >> 4, tx = tid & 15;
    float2 acc[8][4];
#pragma unroll
    for (int i = 0; i < 8; i++)
#pragma unroll
        for (int j = 0; j < 4; j++) acc[i][j] = make_float2(0.f, 0.f);

    int am = tid >> 2;          // 0..63
    int ak = (tid & 3) * 4;     // 0,4,8,12
    int bk = tid >> 5;          // 0..7
    int bn = (tid & 31) * 4;

    for (int k0 = 0; k0 < D_DIM; k0 += BK) {
        // A tile (gathered by token), duplicated for f32x2 broadcast
#pragma unroll
        for (int h = 0; h < 2; h++) {
            int m   = am + h * 64;
            int tok = tok_s[m];
            float4 v = make_float4(0.f, 0.f, 0.f, 0.f);
            if (tok >= 0)
                v = *(const float4*)(x + (size_t)tok * D_DIM + k0 + ak);
            *(float2*)&As2[ak + 0][2 * m] = make_float2(v.x, v.x);
            *(float2*)&As2[ak + 1][2 * m] = make_float2(v.y, v.y);
            *(float2*)&As2[ak + 2][2 * m] = make_float2(v.z, v.z);
            *(float2*)&As2[ak + 3][2 * m] = make_float2(v.w, v.w);
        }
        // B tile
#pragma unroll
        for (int h = 0; h < 2; h++) {
            int k = bk + h * 8;
            *(float4*)&Bs[k][bn] =
                *(const float4*)(Bsrc + (size_t)(k0 + k) * F_DIM + bn);
        }
        __syncthreads();
#pragma unroll
        for (int k = 0; k < BK; k++) {
            float4 a01 = *(float4*)&As2[k][16 * ty + 0];
            float4 a23 = *(float4*)&As2[k][16 * ty + 4];
            float4 a45 = *(float4*)&As2[k][16 * ty + 8];
            float4 a67 = *(float4*)&As2[k][16 * ty + 12];
            float4 bv0 = *(float4*)&Bs[k][tx * 8];
            float4 bv1 = *(float4*)&Bs[k][tx * 8 + 4];
            float2 a[8] = { {a01.x,a01.y},{a01.z,a01.w},{a23.x,a23.y},{a23.z,a23.w},
                            {a45.x,a45.y},{a45.z,a45.w},{a67.x,a67.y},{a67.z,a67.w} };
            float2 b[4] = { {bv0.x,bv0.y},{bv0.z,bv0.w},{bv1.x,bv1.y},{bv1.z,bv1.w} };
#pragma unroll
            for (int i = 0; i < 8; i++)
#pragma unroll
                for (int j = 0; j < 4; j++)
                    acc[i][j] = ffma2(a[i], b[j], acc[i][j]);
        }
        __syncthreads();
    }

    const float* b1e = b1 + e * F_DIM + n0 + tx * 8;
#pragma unroll
    for (int i = 0; i < 8; i++) {
        int r = row0 + ty * 8 + i;
        if (r < n_e) {
            float* Hp = g_H + (size_t)(base + r) * F_DIM + n0 + tx * 8;
#pragma unroll
            for (int j = 0; j < 4; j++) {
                float2 v = acc[i][j];
                v.x = fmaxf(v.x + b1e[2 * j + 0], 0.f);
                v.y = fmaxf(v.y + b1e[2 * j + 1], 0.f);
                *(float2*)(Hp + 2 * j) = v;
            }
        }
    }
}

// GEMM2: out[tok(r), :] += w(r) * (H[r, :] @ w2[e] + b2[e]),  K = F_DIM
__global__ __launch_bounds__(256, 2)
void gemm2_kernel(const float* __restrict__ w2,
                  const float* __restrict__ b2,
                  float* __restrict__ out) {
    int e    = blockIdx.z;
    int n_e  = g_counts[e];
    int row0 = blockIdx.y * BM;
    if (row0 >= n_e) return;
    int base = g_offsets[e];
    int n0   = blockIdx.x * BN;

    __shared__ float As2[BK][AS_LD];
    __shared__ float Bs[BK][BN];

    int tid = threadIdx.x;
    const float* Bsrc = w2 + (size_t)e * F_DIM * D_DIM + n0;
    int ty = tid >> 4, tx = tid & 15;
    float2 acc[8][4];
#pragma unroll
    for (int i = 0; i < 8; i++)
#pragma unroll
        for (int j = 0; j < 4; j++) acc[i][j] = make_float2(0.f, 0.f);

    int am = tid >> 2;
    int ak = (tid & 3) * 4;
    int bk = tid >> 5;
    int bn = (tid & 31) * 4;

    for (int k0 = 0; k0 < F_DIM; k0 += BK) {
#pragma unroll
        for (int h = 0; h < 2; h++) {
            int m  = am + h * 64;
            int rr = row0 + m; if (rr >= n_e) rr = n_e - 1;   // clamp (stay in-bounds)
            float4 v = *(const float4*)(g_H + (size_t)(base + rr) * F_DIM + k0 + ak);
            *(float2*)&As2[ak + 0][2 * m] = make_float2(v.x, v.x);
            *(float2*)&As2[ak + 1][2 * m] = make_float2(v.y, v.y);
            *(float2*)&As2[ak + 2][2 * m] = make_float2(v.z, v.z);
            *(float2*)&As2[ak + 3][2 * m] = make_float2(v.w, v.w);
        }
#pragma unroll
        for (int h = 0; h < 2; h++) {
            int k = bk + h * 8;
            *(float4*)&Bs[k][bn] =
                *(const float4*)(Bsrc + (size_t)(k0 + k) * D_DIM + bn);
        }
        __syncthreads();
#pragma unroll
        for (int k = 0; k < BK; k++) {
            float4 a01 = *(float4*)&As2[k][16 * ty + 0];
            float4 a23 = *(float4*)&As2[k][16 * ty + 4];
            float4 a45 = *(float4*)&As2[k][16 * ty + 8];
            float4 a67 = *(float4*)&As2[k][16 * ty + 12];
            float4 bv0 = *(float4*)&Bs[k][tx * 8];
            float4 bv1 = *(float4*)&Bs[k][tx * 8 + 4];
            float2 a[8] = { {a01.x,a01.y},{a01.z,a01.w},{a23.x,a23.y},{a23.z,a23.w},
                            {a45.x,a45.y},{a45.z,a45.w},{a67.x,a67.y},{a67.z,a67.w} };
            float2 b[4] = { {bv0.x,bv0.y},{bv0.z,bv0.w},{bv1.x,bv1.y},{bv1.z,bv1.w} };
#pragma unroll
            for (int i = 0; i < 8; i++)
#pragma unroll
                for (int j = 0; j < 4; j++)
                    acc[i][j] = ffma2(a[i], b[j], acc[i][j]);
        }
        __syncthreads();
    }

    const float* b2e = b2 + e * D_DIM + n0 + tx * 8;
#pragma unroll
    for (int i = 0; i < 8; i++) {
        int r = row0 + ty * 8 + i;
        if (r < n_e) {
            int   t = g_rows_token[base + r];
            float w = g_rows_w[base + r];
            float* op = out + (size_t)t * D_DIM + n0 + tx * 8;
#pragma unroll
            for (int j = 0; j < 4; j++) {
                float2 v = acc[i][j];
                atomicAdd(op + 2 * j + 0, w * (v.x + b2e[2 * j + 0]));
                atomicAdd(op + 2 * j + 1, w * (v.y + b2e[2 * j + 1]));
            }
        }
    }
}

// ---------------- launch -----------------------------------------------------
extern "C" void kernel_launch(void* const* d_in, const int* in_sizes, int n_in,
                              void* d_out, int out_size) {
    const float* x    = (const float*)d_in[0];
    const int*   mask = (const int*)d_in[1];
    const float* rw   = (const float*)d_in[2];
    const float* w1   = (const float*)d_in[3];
    const float* b1   = (const float*)d_in[4];
    const float* w2   = (const float*)d_in[5];
    const float* b2   = (const float*)d_in[6];
    float*       out  = (float*)d_out;

    cudaMemsetAsync(out, 0, (size_t)T_TOK * D_DIM * sizeof(float));
    init_kernel<<<1, 32>>>();
    router_kernel<<<T_TOK / 8, 256>>>(x, mask, rw);
    offsets_kernel<<<1, 32>>>();
    scatter_kernel<<<(T_TOK + 255) / 256, 256>>>(mask);

    dim3 g1(F_DIM / BN, RMAX / BM, E_NUM);   // (16, 128, 8), empty tiles early-exit
    gemm1_kernel<<<g1, 256>>>(x, w1, b1);
    dim3 g2(D_DIM / BN, RMAX / BM, E_NUM);   // (8, 128, 8)
    gemm2_kernel<<<g2, 256>>>(w2, b2, out);
}

// round 3
// speedup vs baseline: 1.9370x; 1.9370x over previous
#include <cuda_runtime.h>
#include <cuda_bf16.h>
#include <cstdint>

// Problem constants (B=4, S=2048, D=1024, E=8, F=2048, top_k=2)
#define T_TOK 8192
#define D_DIM 1024
#define E_NUM 8
#define F_DIM 2048
#define RMAX  (2 * T_TOK)

#define BM 128
#define BN 128
#define BK 32
#define SMEM_SZ (1024 + 2 * 32768)   // tok list + 2 buffers of (Ah,Al,Bh,Bl)

// ---------------- device scratch (no allocation allowed) --------------------
__device__ __nv_bfloat16 g_Hh[(size_t)RMAX * F_DIM];              // 64 MB
__device__ __nv_bfloat16 g_Hl[(size_t)RMAX * F_DIM];              // 64 MB
__device__ __nv_bfloat16 g_w1t_hi[(size_t)E_NUM * F_DIM * D_DIM]; // [E][F][D]
__device__ __nv_bfloat16 g_w1t_lo[(size_t)E_NUM * F_DIM * D_DIM];
__device__ __nv_bfloat16 g_w2t_hi[(size_t)E_NUM * D_DIM * F_DIM]; // [E][D][F]
__device__ __nv_bfloat16 g_w2t_lo[(size_t)E_NUM * D_DIM * F_DIM];
__device__ int   g_rows_token[RMAX];
__device__ float g_rows_w[RMAX];
__device__ int   g_top_i[2 * T_TOK];
__device__ float g_top_w[2 * T_TOK];
__device__ int   g_counts[E_NUM];
__device__ int   g_offsets[E_NUM];
__device__ int   g_cursor[E_NUM];

// ---------------- helpers ----------------------------------------------------
__device__ __forceinline__ uint32_t smem_u32(const void* p) {
    uint32_t a;
    asm("{ .reg .u64 t; cvta.to.shared.u64 t, %1; cvt.u32.u64 %0, t; }"
        : "=r"(a) : "l"(p));
    return a;
}
// 64B-row swizzle: chunk(16B) index ^= (row & 3)
#define SWZ64(o) ((o) ^ (((o) >> 2) & 0x30))

__device__ __forceinline__ void ldsm4(uint32_t* r, uint32_t addr) {
    asm volatile("ldmatrix.sync.aligned.m8n8.x4.shared.b16 {%0,%1,%2,%3}, [%4];"
                 : "=r"(r[0]), "=r"(r[1]), "=r"(r[2]), "=r"(r[3]) : "r"(addr));
}
__device__ __forceinline__ void mma16816(float* c, const uint32_t* a,
                                         const uint32_t* b) {
    asm volatile(
        "mma.sync.aligned.m16n8k16.row.col.f32.bf16.bf16.f32 "
        "{%0,%1,%2,%3}, {%4,%5,%6,%7}, {%8,%9}, {%0,%1,%2,%3};"
        : "+f"(c[0]), "+f"(c[1]), "+f"(c[2]), "+f"(c[3])
        : "r"(a[0]), "r"(a[1]), "r"(a[2]), "r"(a[3]), "r"(b[0]), "r"(b[1]));
}

// fp32x8 -> bf16 hi/lo packed
__device__ __forceinline__ void cvt8(float4 v0, float4 v1, uint4& h, uint4& l) {
    float f[8] = {v0.x, v0.y, v0.z, v0.w, v1.x, v1.y, v1.z, v1.w};
    uint32_t hh[4], ll[4];
#pragma unroll
    for (int p = 0; p < 4; p++) {
        float2 a = make_float2(f[2 * p], f[2 * p + 1]);
        __nv_bfloat162 H = __float22bfloat162_rn(a);
        float2 bk = __bfloat1622float2(H);
        __nv_bfloat162 L = __float22bfloat162_rn(make_float2(a.x - bk.x, a.y - bk.y));
        hh[p] = *reinterpret_cast<uint32_t*>(&H);
        ll[p] = *reinterpret_cast<uint32_t*>(&L);
    }
    h = make_uint4(hh[0], hh[1], hh[2], hh[3]);
    l = make_uint4(ll[0], ll[1], ll[2], ll[3]);
}

// ---------------- init / router / scatter (validated in R1) ------------------
__global__ void init_kernel() {
    int i = threadIdx.x;
    if (i < E_NUM) { g_counts[i] = 0; g_cursor[i] = 0; }
}

__global__ void router_kernel(const float* __restrict__ x,
                              const int* __restrict__ mask,
                              const float* __restrict__ rw) {
    __shared__ float rws[E_NUM * D_DIM];
    for (int i = threadIdx.x; i < E_NUM * D_DIM; i += blockDim.x) {
        int d = i >> 3, e = i & 7;
        rws[e * D_DIM + d] = rw[i];
    }
    __syncthreads();

    int wid  = blockIdx.x * (blockDim.x >> 5) + (threadIdx.x >> 5);
    int lane = threadIdx.x & 31;
    if (wid >= T_TOK) return;

    const float* xp = x + (size_t)wid * D_DIM;
    float xr[32];
#pragma unroll
    for (int j = 0; j < 32; j++) xr[j] = xp[lane + 32 * j];

    float lg[E_NUM];
#pragma unroll
    for (int e = 0; e < E_NUM; e++) {
        float acc = 0.f;
#pragma unroll
        for (int j = 0; j < 32; j++)
            acc = fmaf(xr[j], rws[e * D_DIM + lane + 32 * j], acc);
#pragma unroll
        for (int o = 16; o; o >>= 1) acc += __shfl_xor_sync(0xffffffffu, acc, o);
        lg[e] = acc;
    }

    if (lane == 0) {
        int i0 = 0; float v0 = lg[0];
#pragma unroll
        for (int e = 1; e < E_NUM; e++) if (lg[e] > v0) { v0 = lg[e]; i0 = e; }
        int i1 = -1; float v1 = -3.0e38f;
#pragma unroll
        for (int e = 0; e < E_NUM; e++)
            if (e != i0 && lg[e] > v1) { v1 = lg[e]; i1 = e; }
        float r = expf(v1 - v0);
        float s = 1.f + r;
        g_top_i[2 * wid] = i0;  g_top_i[2 * wid + 1] = i1;
        g_top_w[2 * wid] = 1.f / s;  g_top_w[2 * wid + 1] = r / s;
        if (mask[wid] != 0) {
            atomicAdd(&g_counts[i0], 1);
            atomicAdd(&g_counts[i1], 1);
        }
    }
}

__global__ void offsets_kernel() {
    if (threadIdx.x == 0) {
        int s = 0;
        for (int e = 0; e < E_NUM; e++) { g_offsets[e] = s; s += g_counts[e]; }
    }
}

__global__ void scatter_kernel(const int* __restrict__ mask) {
    int t = blockIdx.x * blockDim.x + threadIdx.x;
    if (t >= T_TOK || mask[t] == 0) return;
#pragma unroll
    for (int k = 0; k < 2; k++) {
        int e   = g_top_i[2 * t + k];
        int pos = atomicAdd(&g_cursor[e], 1);
        int idx = g_offsets[e] + pos;
        g_rows_token[idx] = t;
        g_rows_w[idx]     = g_top_w[2 * t + k];
    }
}

// ---------------- weight transpose + bf16 hi/lo split ------------------------
__device__ __forceinline__ void transpose_body(const float* __restrict__ in,
                                               __nv_bfloat16* __restrict__ ohi,
                                               __nv_bfloat16* __restrict__ olo,
                                               int K, int N) {
    __shared__ float t[32][33];
    int k0 = blockIdx.y * 32, n0 = blockIdx.x * 32;
    size_t ebase = (size_t)blockIdx.z * K * N;
    const float* p = in + ebase + (size_t)k0 * N + n0;
#pragma unroll
    for (int i = 0; i < 4; i++)
        t[threadIdx.y + 8 * i][threadIdx.x] =
            p[(size_t)(threadIdx.y + 8 * i) * N + threadIdx.x];
    __syncthreads();
#pragma unroll
    for (int i = 0; i < 4; i++) {
        int n = n0 + threadIdx.y + 8 * i;
        float v = t[threadIdx.x][threadIdx.y + 8 * i];
        __nv_bfloat16 hi = __float2bfloat16(v);
        __nv_bfloat16 lo = __float2bfloat16(v - __bfloat162float(hi));
        size_t o = ebase + (size_t)n * K + k0 + threadIdx.x;
        ohi[o] = hi;
        olo[o] = lo;
    }
}
__global__ void convert_w1(const float* __restrict__ w) {
    transpose_body(w, g_w1t_hi, g_w1t_lo, D_DIM, F_DIM);
}
__global__ void convert_w2(const float* __restrict__ w) {
    transpose_body(w, g_w2t_hi, g_w2t_lo, F_DIM, D_DIM);
}

// ---------------- grouped GEMM via mma.sync (split-bf16 x3) ------------------
// G1: H[r,:]  = relu(x[tok(r),:] @ w1[e] + b1[e])      K=1024, N=2048
// G2: out[t,:] += w(r) * (H[r,:] @ w2[e] + b2[e])      K=2048, N=1024
template <bool G1>
__global__ __launch_bounds__(256, 1)
void gemm_kernel(const float* __restrict__ xsrc,
                 const float* __restrict__ bias,
                 float* __restrict__ outp) {
    constexpr int KTOT = G1 ? D_DIM : F_DIM;
    constexpr int NTOT = G1 ? F_DIM : D_DIM;
    constexpr int NCH  = KTOT / BK;

    extern __shared__ char smem[];
    const uint32_t sb = smem_u32(smem);
    int* tok_s = (int*)smem;                 // [0,512)
    const int BUF0 = 1024;                   // 2 x 32KB buffers
    // buffer layout: Ah 0 | Al 8192 | Bh 16384 | Bl 24576  (rows of 64B)

    int e    = blockIdx.z;
    int n_e  = g_counts[e];
    int row0 = blockIdx.y * BM;
    if (row0 >= n_e) return;
    int base = g_offsets[e];
    int n0   = blockIdx.x * BN;

    int tid  = threadIdx.x;
    int w    = tid >> 5, lane = tid & 31;
    int wm   = w >> 2, wn = w & 3;           // 2 x 4 warp grid; warp tile 64m x 32n

    if (G1 && tid < BM) {
        int r = row0 + tid;
        tok_s[tid] = (r < n_e) ? g_rows_token[base + r] : -1;
    }
    __syncthreads();

    const __nv_bfloat16* Bhi;
    const __nv_bfloat16* Blo;
    if constexpr (G1) {
        Bhi = g_w1t_hi + ((size_t)e * F_DIM + n0) * D_DIM;
        Blo = g_w1t_lo + ((size_t)e * F_DIM + n0) * D_DIM;
    } else {
        Bhi = g_w2t_hi + ((size_t)e * D_DIM + n0) * F_DIM;
        Blo = g_w2t_lo + ((size_t)e * D_DIM + n0) * F_DIM;
    }

    // per-thread load/store geometry: row = tid>>1, 16 elements at (tid&1)*16
    int lrow = tid >> 1, lhalf = tid & 1;
    int sbyte = lrow * 64 + lhalf * 32;      // within one 8KB matrix tile

    uint4 rAh[2], rAl[2], rBh[2], rBl[2];

    auto load_g = [&](int c) {
        int k0 = c * BK;
        // ---- A ----
        if constexpr (G1) {
            int tk = tok_s[lrow];
            if (tk >= 0) {
                const float* ap = xsrc + (size_t)tk * D_DIM + k0 + lhalf * 16;
                float4 v0 = *(const float4*)(ap + 0);
                float4 v1 = *(const float4*)(ap + 4);
                float4 v2 = *(const float4*)(ap + 8);
                float4 v3 = *(const float4*)(ap + 12);
                cvt8(v0, v1, rAh[0], rAl[0]);
                cvt8(v2, v3, rAh[1], rAl[1]);
            } else {
                rAh[0] = rAh[1] = rAl[0] = rAl[1] = make_uint4(0, 0, 0, 0);
            }
        } else {
            int rr = row0 + lrow; if (rr >= n_e) rr = n_e - 1;
            size_t ao = (size_t)(base + rr) * F_DIM + k0 + lhalf * 16;
            rAh[0] = *(const uint4*)(g_Hh + ao);
            rAh[1] = *(const uint4*)(g_Hh + ao + 8);
            rAl[0] = *(const uint4*)(g_Hl + ao);
            rAl[1] = *(const uint4*)(g_Hl + ao + 8);
        }
        // ---- B ----
        size_t bo = (size_t)lrow * KTOT + k0 + lhalf * 16;
        rBh[0] = *(const uint4*)(Bhi + bo);
        rBh[1] = *(const uint4*)(Bhi + bo + 8);
        rBl[0] = *(const uint4*)(Blo + bo);
        rBl[1] = *(const uint4*)(Blo + bo + 8);
    };

    auto sts = [&](int b) {
        char* bp = smem + BUF0 + b * 32768;
        *(uint4*)(bp + 0     + SWZ64(sbyte))      = rAh[0];
        *(uint4*)(bp + 0     + SWZ64(sbyte + 16)) = rAh[1];
        *(uint4*)(bp + 8192  + SWZ64(sbyte))      = rAl[0];
        *(uint4*)(bp + 8192  + SWZ64(sbyte + 16)) = rAl[1];
        *(uint4*)(bp + 16384 + SWZ64(sbyte))      = rBh[0];
        *(uint4*)(bp + 16384 + SWZ64(sbyte + 16)) = rBh[1];
        *(uint4*)(bp + 24576 + SWZ64(sbyte))      = rBl[0];
        *(uint4*)(bp + 24576 + SWZ64(sbyte + 16)) = rBl[1];
    };

    float acc[4][4][4];
#pragma unroll
    for (int i = 0; i < 4; i++)
#pragma unroll
        for (int j = 0; j < 4; j++)
#pragma unroll
            for (int q = 0; q < 4; q++) acc[i][j][q] = 0.f;

    // ldmatrix lane-address components
    int aRow = (lane & 7) + ((lane >> 3) & 1) * 8;   // + m-frag base
    int aKc  = (lane >> 4);                          // + ks*2
    int bRow = (lane & 7) + (lane >> 4) * 8;         // + n-frag-pair base
    int bKc  = (lane >> 3) & 1;                      // + ks*2

    load_g(0);
    sts(0);
    __syncthreads();

    for (int c = 0; c < NCH; c++) {
        int b = c & 1;
        if (c + 1 < NCH) load_g(c + 1);

        uint32_t bufA = sb + BUF0 + b * 32768;
        uint32_t bufB = bufA + 16384;
#pragma unroll
        for (int ks = 0; ks < 2; ks++) {
            uint32_t fAh[4][4], fAl[4][4], fB[2][8];   // fB: [hi/lo][4 nfrags x 2]
#pragma unroll
            for (int mf = 0; mf < 4; mf++) {
                int row = wm * 64 + mf * 16 + aRow;
                int off = SWZ64(row * 64 + (ks * 2 + aKc) * 16);
                ldsm4(fAh[mf], bufA + off);
                ldsm4(fAl[mf], bufA + 8192 + off);
            }
#pragma unroll
            for (int h = 0; h < 2; h++) {
#pragma unroll
                for (int p = 0; p < 2; p++) {
                    int row = wn * 32 + p * 16 + bRow;
                    int off = SWZ64(row * 64 + (ks * 2 + bKc) * 16);
                    ldsm4(&fB[h][p * 4], bufB + h * 8192 + off);
                }
            }
#pragma unroll
            for (int mf = 0; mf < 4; mf++)
#pragma unroll
                for (int nf = 0; nf < 4; nf++) {
                    mma16816(acc[mf][nf], fAh[mf], &fB[0][nf * 2]);  // Ah*Bh
                    mma16816(acc[mf][nf], fAh[mf], &fB[1][nf * 2]);  // Ah*Bl
                    mma16816(acc[mf][nf], fAl[mf], &fB[0][nf * 2]);  // Al*Bh
                }
        }
        if (c + 1 < NCH) sts((c + 1) & 1);
        __syncthreads();
    }

    // ---------------- epilogue ----------------
    int g  = lane >> 2, t4 = lane & 3;
    // preload bias for this thread's 8 columns
    float bia[4][2];
#pragma unroll
    for (int nf = 0; nf < 4; nf++) {
        int col = n0 + wn * 32 + nf * 8 + t4 * 2;
        bia[nf][0] = bias[(size_t)e * NTOT + col];
        bia[nf][1] = bias[(size_t)e * NTOT + col + 1];
    }

    if constexpr (G1) {
#pragma unroll
        for (int mf = 0; mf < 4; mf++) {
#pragma unroll
            for (int half = 0; half < 2; half++) {
                int r = row0 + wm * 64 + mf * 16 + g + half * 8;
                if (r < n_e) {
                    size_t ro = (size_t)(base + r) * F_DIM;
#pragma unroll
                    for (int nf = 0; nf < 4; nf++) {
                        int col = n0 + wn * 32 + nf * 8 + t4 * 2;
                        float v0 = fmaxf(acc[mf][nf][2 * half + 0] + bia[nf][0], 0.f);
                        float v1 = fmaxf(acc[mf][nf][2 * half + 1] + bia[nf][1], 0.f);
                        __nv_bfloat162 H = __float22bfloat162_rn(make_float2(v0, v1));
                        float2 bk = __bfloat1622float2(H);
                        __nv_bfloat162 L = __float22bfloat162_rn(
                            make_float2(v0 - bk.x, v1 - bk.y));
                        *(uint32_t*)(g_Hh + ro + col) = *reinterpret_cast<uint32_t*>(&H);
                        *(uint32_t*)(g_Hl + ro + col) = *reinterpret_cast<uint32_t*>(&L);
                    }
                }
            }
        }
    } else {
#pragma unroll
        for (int mf = 0; mf < 4; mf++) {
#pragma unroll
            for (int half = 0; half < 2; half++) {
                int r = row0 + wm * 64 + mf * 16 + g + half * 8;
                if (r < n_e) {
                    int   t = g_rows_token[base + r];
                    float ww = g_rows_w[base + r];
                    float* op = outp + (size_t)t * D_DIM;
#pragma unroll
                    for (int nf = 0; nf < 4; nf++) {
                        int col = n0 + wn * 32 + nf * 8 + t4 * 2;
                        atomicAdd(op + col,
                                  ww * (acc[mf][nf][2 * half + 0] + bia[nf][0]));
                        atomicAdd(op + col + 1,
                                  ww * (acc[mf][nf][2 * half + 1] + bia[nf][1]));
                    }
                }
            }
        }
    }
}

// ---------------- launch -----------------------------------------------------
extern "C" void kernel_launch(void* const* d_in, const int* in_sizes, int n_in,
                              void* d_out, int out_size) {
    const float* x    = (const float*)d_in[0];
    const int*   mask = (const int*)d_in[1];
    const float* rw   = (const float*)d_in[2];
    const float* w1   = (const float*)d_in[3];
    const float* b1   = (const float*)d_in[4];
    const float* w2   = (const float*)d_in[5];
    const float* b2   = (const float*)d_in[6];
    float*       out  = (float*)d_out;

    cudaFuncSetAttribute(gemm_kernel<true>,
                         cudaFuncAttributeMaxDynamicSharedMemorySize, SMEM_SZ);
    cudaFuncSetAttribute(gemm_kernel<false>,
                         cudaFuncAttributeMaxDynamicSharedMemorySize, SMEM_SZ);

    cudaMemsetAsync(out, 0, (size_t)T_TOK * D_DIM * sizeof(float));
    init_kernel<<<1, 32>>>();

    convert_w1<<<dim3(F_DIM / 32, D_DIM / 32, E_NUM), dim3(32, 8)>>>(w1);
    convert_w2<<<dim3(D_DIM / 32, F_DIM / 32, E_NUM), dim3(32, 8)>>>(w2);

    router_kernel<<<T_TOK / 8, 256>>>(x, mask, rw);
    offsets_kernel<<<1, 32>>>();
    scatter_kernel<<<(T_TOK + 255) / 256, 256>>>(mask);

    dim3 g1(F_DIM / BN, RMAX / BM, E_NUM);
    gemm_kernel<true><<<g1, 256, SMEM_SZ>>>(x, b1, out);
    dim3 g2(D_DIM / BN, RMAX / BM, E_NUM);
    gemm_kernel<false><<<g2, 256, SMEM_SZ>>>(x, b2, out);
}